// round 3
// baseline (speedup 1.0000x reference)
#include <cuda_runtime.h>
#include <cuda_bf16.h>
#include <math.h>

// Problem constants
#define TT 512
#define NN 32
#define CC 1296
#define DD 512
#define SS 30
#define LL 61           // 2*S+1
#define MM (TT*NN)      // 16384 rows
#define NORM_SCALE 32.0f
#define NEGINF (-1e9f)

// ---------------- scratch (device globals; no allocations allowed) ----------------
__device__ float g_wn[DD * CC];        // normalized classifier weight (D, C)
__device__ float g_scale[MM];          // 32 / ||feat_row||
__device__ float g_logits[(size_t)MM * CC];   // full logits (85 MB)
__device__ float g_lp[MM * 32];        // per-row: [0]=logprob(blank), [1..30]=logprob(labels[n])
__device__ float g_nll[NN];

// ---------------- 1. normalize classifier weight columns ----------------
__global__ void wnorm_kernel(const float* __restrict__ w) {
    int c = blockIdx.x * blockDim.x + threadIdx.x;
    if (c >= CC) return;
    float ss = 0.f;
    #pragma unroll 8
    for (int d = 0; d < DD; d++) { float v = w[d * CC + c]; ss += v * v; }
    float inv = rsqrtf(ss);
    #pragma unroll 8
    for (int d = 0; d < DD; d++) g_wn[d * CC + c] = w[d * CC + c] * inv;
}

// ---------------- 2. per-row scale = 32 / ||f|| ----------------
__global__ void fscale_kernel(const float* __restrict__ f) {
    int row = blockIdx.x * (blockDim.x >> 5) + (threadIdx.x >> 5);
    int lane = threadIdx.x & 31;
    if (row >= MM) return;
    const float4* fr = (const float4*)(f + (size_t)row * DD);
    float ss = 0.f;
    #pragma unroll
    for (int i = lane; i < DD / 4; i += 32) {
        float4 v = fr[i];
        ss += v.x * v.x + v.y * v.y + v.z * v.z + v.w * v.w;
    }
    #pragma unroll
    for (int o = 16; o; o >>= 1) ss += __shfl_xor_sync(0xffffffffu, ss, o);
    if (lane == 0) g_scale[row] = NORM_SCALE * rsqrtf(ss);
}

// ---------------- 3. SGEMM: logits = scale[m] * (feats @ w_n) ----------------
#define BM 128
#define BN 64
#define BK 16
#define NKT (DD / BK)   // 32 k-tiles

__global__ void __launch_bounds__(256) gemm_kernel(const float* __restrict__ A) {
    __shared__ float As[2][BK][BM];
    __shared__ float Bs[2][BK][BN];

    const int bm = blockIdx.y * BM;
    const int bn = blockIdx.x * BN;
    const int tid = threadIdx.x;
    const int tx = tid & 15;       // 0..15 -> 4-col group
    const int ty = tid >> 4;       // 0..15 -> 8-row group
    // A loader: 2 float4 per thread (128 rows x 16 k)
    const int ar = tid >> 2;            // 0..63
    const int ak = (tid & 3) * 4;       // 0,4,8,12
    // B loader: 1 float4 per thread (16 rows x 64 cols)
    const int br = tid >> 4;            // 0..15
    const int bc = (tid & 15) * 4;      // 0..60

    float acc[8][4];
    #pragma unroll
    for (int i = 0; i < 8; i++)
        #pragma unroll
        for (int j = 0; j < 4; j++) acc[i][j] = 0.f;

    // initial tile -> buffer 0
    {
        #pragma unroll
        for (int h = 0; h < 2; h++) {
            int row = ar + h * 64;
            float4 v = *(const float4*)(A + (size_t)(bm + row) * DD + ak);
            As[0][ak + 0][row] = v.x;
            As[0][ak + 1][row] = v.y;
            As[0][ak + 2][row] = v.z;
            As[0][ak + 3][row] = v.w;
        }
        int col = bn + bc;
        float4 v = make_float4(0.f, 0.f, 0.f, 0.f);
        if (col < CC) v = *(const float4*)(g_wn + (size_t)br * CC + col);
        *(float4*)&Bs[0][br][bc] = v;
    }
    __syncthreads();

    #pragma unroll 1
    for (int kt = 0; kt < NKT; kt++) {
        const int buf = kt & 1;
        float4 a_next0, a_next1, b_next;
        const bool more = (kt + 1 < NKT);
        if (more) {
            int k0 = (kt + 1) * BK;
            a_next0 = *(const float4*)(A + (size_t)(bm + ar) * DD + k0 + ak);
            a_next1 = *(const float4*)(A + (size_t)(bm + ar + 64) * DD + k0 + ak);
            int col = bn + bc;
            b_next = make_float4(0.f, 0.f, 0.f, 0.f);
            if (col < CC) b_next = *(const float4*)(g_wn + (size_t)(k0 + br) * CC + col);
        }
        #pragma unroll
        for (int kk = 0; kk < BK; kk++) {
            float a0[8], b0[4];
            *(float4*)&a0[0] = *(float4*)&As[buf][kk][ty * 8];
            *(float4*)&a0[4] = *(float4*)&As[buf][kk][ty * 8 + 4];
            *(float4*)&b0[0] = *(float4*)&Bs[buf][kk][tx * 4];
            #pragma unroll
            for (int i = 0; i < 8; i++)
                #pragma unroll
                for (int j = 0; j < 4; j++)
                    acc[i][j] += a0[i] * b0[j];
        }
        if (more) {
            const int nb = buf ^ 1;
            As[nb][ak + 0][ar] = a_next0.x;
            As[nb][ak + 1][ar] = a_next0.y;
            As[nb][ak + 2][ar] = a_next0.z;
            As[nb][ak + 3][ar] = a_next0.w;
            As[nb][ak + 0][ar + 64] = a_next1.x;
            As[nb][ak + 1][ar + 64] = a_next1.y;
            As[nb][ak + 2][ar + 64] = a_next1.z;
            As[nb][ak + 3][ar + 64] = a_next1.w;
            *(float4*)&Bs[nb][br][bc] = b_next;
        }
        __syncthreads();
    }

    // epilogue: apply per-row scale, write logits
    const int col = bn + tx * 4;
    if (col < CC) {
        #pragma unroll
        for (int i = 0; i < 8; i++) {
            int row = bm + ty * 8 + i;
            float s = g_scale[row];
            float4 o;
            o.x = s * acc[i][0];
            o.y = s * acc[i][1];
            o.z = s * acc[i][2];
            o.w = s * acc[i][3];
            *(float4*)(g_logits + (size_t)row * CC + col) = o;
        }
    }
}

// ---------------- 4. per-row logsumexp + gather needed classes ----------------
__global__ void __launch_bounds__(256) lse_kernel(const int* __restrict__ labeling) {
    const int m = blockIdx.x;
    const float* lr = g_logits + (size_t)m * CC;
    const int tid = threadIdx.x;
    __shared__ float red[8];
    __shared__ float s_lse;

    float mx = -1e30f;
    for (int i = tid; i < CC; i += 256) mx = fmaxf(mx, lr[i]);
    #pragma unroll
    for (int o = 16; o; o >>= 1) mx = fmaxf(mx, __shfl_xor_sync(0xffffffffu, mx, o));
    if ((tid & 31) == 0) red[tid >> 5] = mx;
    __syncthreads();
    if (tid < 32) {
        float v = (tid < 8) ? red[tid] : -1e30f;
        #pragma unroll
        for (int o = 4; o; o >>= 1) v = fmaxf(v, __shfl_xor_sync(0xffffffffu, v, o));
        if (tid == 0) red[0] = v;
    }
    __syncthreads();
    mx = red[0];
    __syncthreads();

    float s = 0.f;
    for (int i = tid; i < CC; i += 256) s += __expf(lr[i] - mx);
    #pragma unroll
    for (int o = 16; o; o >>= 1) s += __shfl_xor_sync(0xffffffffu, s, o);
    if ((tid & 31) == 0) red[tid >> 5] = s;
    __syncthreads();
    if (tid == 0) {
        float t2 = 0.f;
        #pragma unroll
        for (int w = 0; w < 8; w++) t2 += red[w];
        s_lse = mx + logf(t2);
    }
    __syncthreads();
    const float lse = s_lse;

    if (tid < 31) {
        int n = m & 31;
        int cls = (tid == 0) ? 0 : labeling[n * SS + tid - 1];
        g_lp[m * 32 + tid] = lr[cls] - lse;
    }
}

// ---------------- 5. CTC forward recursion (1 block per sample) ----------------
__global__ void __launch_bounds__(64) ctc_kernel(const int* __restrict__ labeling,
                                                 const int* __restrict__ in_lens,
                                                 const int* __restrict__ lab_lens) {
    const int n = blockIdx.x;
    const int s = threadIdx.x;         // 0..63 (states 0..60 valid)
    __shared__ float abuf[66];         // abuf[0..1] are pads; alpha = abuf+2
    float* alpha = abuf + 2;

    const bool valid = (s < LL);
    const bool odd = (s & 1) != 0;
    int lpidx = 0;
    if (valid) lpidx = odd ? (1 + (s >> 1)) : 0;

    bool skip = false;
    if (valid && odd && s >= 3) {
        int l1 = labeling[n * SS + (s >> 1)];
        int l0 = labeling[n * SS + (s >> 1) - 1];
        skip = (l1 != l0);
    }

    if (s < 2) abuf[s] = NEGINF;
    float a_init = NEGINF;
    if (s == 0) a_init = g_lp[n * 32 + 0];
    else if (s == 1) a_init = g_lp[n * 32 + 1];
    alpha[s] = a_init;
    const int Tn = in_lens[n];
    __syncthreads();

    for (int t = 1; t < Tn; t++) {
        float a1 = alpha[s];
        float a2 = alpha[s - 1];
        float a3 = skip ? alpha[s - 2] : NEGINF;
        float lp = valid ? g_lp[((t * NN) + n) * 32 + lpidx] : NEGINF;
        __syncthreads();
        float m = fmaxf(a1, fmaxf(a2, a3));
        float nv = m + __logf(__expf(a1 - m) + __expf(a2 - m) + __expf(a3 - m)) + lp;
        alpha[s] = nv;
        __syncthreads();
    }

    if (s == 0) {
        int Ln = 2 * lab_lens[n] + 1;
        float x = alpha[Ln - 1], y = alpha[Ln - 2];
        float mm2 = fmaxf(x, y);
        g_nll[n] = -(mm2 + __logf(__expf(x - mm2) + __expf(y - mm2)));
    }
}

// ---------------- 6. deterministic final sum ----------------
__global__ void sum_kernel(float* __restrict__ out) {
    if (threadIdx.x == 0) {
        float t = 0.f;
        #pragma unroll
        for (int i = 0; i < NN; i++) t += g_nll[i];
        out[0] = t;
    }
}

// ---------------- launch ----------------
extern "C" void kernel_launch(void* const* d_in, const int* in_sizes, int n_in,
                              void* d_out, int out_size) {
    const float* feats = (const float*)d_in[0];       // (T*N, D)
    const float* weight = (const float*)d_in[1];      // (D, C)
    const int* labeling = (const int*)d_in[2];        // (N, S)
    const int* logit_lgts = (const int*)d_in[3];      // (N,)
    const int* labeling_lgts = (const int*)d_in[4];   // (N,)
    float* out = (float*)d_out;

    wnorm_kernel<<<(CC + 255) / 256, 256>>>(weight);
    fscale_kernel<<<MM / 8, 256>>>(feats);
    dim3 ggrid((CC + BN - 1) / BN, MM / BM);
    gemm_kernel<<<ggrid, 256>>>(feats);
    lse_kernel<<<MM, 256>>>(labeling);
    ctc_kernel<<<NN, 64>>>(labeling, logit_lgts, labeling_lgts);
    sum_kernel<<<1, 32>>>(out);
}

// round 5
// speedup vs baseline: 1.2515x; 1.2515x over previous
#include <cuda_runtime.h>
#include <cuda_bf16.h>
#include <math.h>
#include <stdint.h>

// Problem constants
#define TT 512
#define NN 32
#define CC 1296
#define DD 512
#define SS 30
#define LL 61
#define MM (TT*NN)              // 16384
#define NORM_SCALE 32.0f
#define NEGINF (-1e9f)
#define CPAD 1536               // padded C for clean tiles (zero-filled)

// ---------------- scratch ----------------
__device__ __nv_bfloat16 g_fb[(size_t)MM * DD];     // feats bf16, row-major [m][d]
__device__ __nv_bfloat16 g_wb[(size_t)CPAD * DD];   // normalized weight, transposed [c][d]
__device__ float g_scale[MM];
__device__ float g_logitsT[(size_t)CC * MM];        // logits transposed [c][m] (85MB)
__device__ float g_lp[32 * MM];                     // [i][m]: i=0 blank, 1..30 labels
__device__ float g_nll[NN];

// ---------------- helpers ----------------
__device__ __forceinline__ uint32_t smem_u32(const void* p) {
    uint32_t a;
    asm("{ .reg .u64 t; cvta.to.shared.u64 t, %1; cvt.u32.u64 %0, t; }" : "=r"(a) : "l"(p));
    return a;
}
__device__ __forceinline__ void cp_async16(uint32_t sa, const void* ga) {
    asm volatile("cp.async.cg.shared.global [%0], [%1], 16;" :: "r"(sa), "l"(ga) : "memory");
}
#define CP_COMMIT() asm volatile("cp.async.commit_group;" ::: "memory")
#define CP_WAIT(n)  asm volatile("cp.async.wait_group %0;" :: "n"(n) : "memory")

__device__ __forceinline__ void ldsm4(uint32_t& r0, uint32_t& r1, uint32_t& r2, uint32_t& r3,
                                      uint32_t addr) {
    asm volatile("ldmatrix.sync.aligned.m8n8.x4.shared.b16 {%0,%1,%2,%3}, [%4];"
                 : "=r"(r0), "=r"(r1), "=r"(r2), "=r"(r3) : "r"(addr));
}
__device__ __forceinline__ void mma16816(float* d, const uint32_t* a, uint32_t b0, uint32_t b1) {
    asm volatile("mma.sync.aligned.m16n8k16.row.col.f32.bf16.bf16.f32 "
                 "{%0,%1,%2,%3}, {%4,%5,%6,%7}, {%8,%9}, {%0,%1,%2,%3};"
                 : "+f"(d[0]), "+f"(d[1]), "+f"(d[2]), "+f"(d[3])
                 : "r"(a[0]), "r"(a[1]), "r"(a[2]), "r"(a[3]), "r"(b0), "r"(b1));
}

// ---------------- 1. normalize weight columns -> transposed bf16 [c][d] ----------------
__global__ void wnorm_kernel(const float* __restrict__ w) {
    int c = blockIdx.x * blockDim.x + threadIdx.x;
    if (c >= CPAD) return;
    if (c >= CC) {
        for (int d = 0; d < DD; d++) g_wb[(size_t)c * DD + d] = __float2bfloat16(0.f);
        return;
    }
    float ss = 0.f;
    #pragma unroll 8
    for (int d = 0; d < DD; d++) { float v = w[d * CC + c]; ss += v * v; }
    float inv = rsqrtf(ss);
    #pragma unroll 8
    for (int d = 0; d < DD; d++)
        g_wb[(size_t)c * DD + d] = __float2bfloat16(w[d * CC + c] * inv);
}

// ---------------- 2. per-row scale + bf16 convert ----------------
__global__ void fscale_kernel(const float* __restrict__ f) {
    int row = blockIdx.x * (blockDim.x >> 5) + (threadIdx.x >> 5);
    int lane = threadIdx.x & 31;
    if (row >= MM) return;
    const float4* fr = (const float4*)(f + (size_t)row * DD);
    __nv_bfloat16* ob = g_fb + (size_t)row * DD;
    float ss = 0.f;
    #pragma unroll
    for (int i = lane; i < DD / 4; i += 32) {
        float4 v = fr[i];
        ss += v.x * v.x + v.y * v.y + v.z * v.z + v.w * v.w;
        ob[i * 4 + 0] = __float2bfloat16(v.x);
        ob[i * 4 + 1] = __float2bfloat16(v.y);
        ob[i * 4 + 2] = __float2bfloat16(v.z);
        ob[i * 4 + 3] = __float2bfloat16(v.w);
    }
    #pragma unroll
    for (int o = 16; o; o >>= 1) ss += __shfl_xor_sync(0xffffffffu, ss, o);
    if (lane == 0) g_scale[row] = NORM_SCALE * rsqrtf(ss);
}

// ---------------- 3. bf16 mma.sync GEMM: logitsT[c][m] = scale[m]*(f@wT) ----------------
// Tile: BM=128, BN=128, BK=64. 256 threads = 8 warps (4 m x 2 n).
// Warp tile: 32m x 64n = 2 m16-tiles x 8 n8-tiles (m16n8k16).
// Smem: [128 rows][64 k] bf16 per operand, SW128 swizzle, double buffered.
#define GBK 64
#define KCH (DD / GBK)          // 8
#define TILE_B 16384            // 128 rows * 128B
#define GEMM_SMEM (2 * 2 * TILE_B + 1024)

__global__ void __launch_bounds__(256) gemm_kernel() {
    extern __shared__ char smraw[];
    const uint32_t base = (smem_u32(smraw) + 1023u) & ~1023u;
    // buffers: A0, B0, A1, B1
    const int tid = threadIdx.x;
    const int wid = tid >> 5;
    const int lane = tid & 31;
    const int bm = blockIdx.y * 128;
    const int bn = blockIdx.x * 128;
    const int wm = (wid >> 1) * 32;      // warp m offset
    const int wn = (wid & 1) * 64;       // warp n offset

    // loader indices: 1024 16B-chunks per tile / 256 thr = 4 each
    // chunk s: row = s>>3, kchunk = s&7 ; swizzled smem chunk = kchunk ^ (row&7)
    auto load_tile = [&](uint32_t sbuf, const __nv_bfloat16* gsrc, int kt) {
        const char* g = (const char*)gsrc + (size_t)kt * 128;
        #pragma unroll
        for (int r = 0; r < 4; r++) {
            int s = tid + r * 256;
            int row = s >> 3, kc = s & 7;
            cp_async16(sbuf + (uint32_t)(row * 128 + ((kc ^ (row & 7)) * 16)),
                       g + (size_t)row * 1024 + kc * 16);
        }
    };
    auto load_chunk = [&](int kt) {
        uint32_t off = (kt & 1) * 2 * TILE_B;
        load_tile(base + off, g_fb + (size_t)bm * DD, kt);
        load_tile(base + off + TILE_B, g_wb + (size_t)bn * DD, kt);
        CP_COMMIT();
    };

    float acc[2][8][4];
    #pragma unroll
    for (int i = 0; i < 2; i++)
        #pragma unroll
        for (int j = 0; j < 8; j++)
            #pragma unroll
            for (int r = 0; r < 4; r++) acc[i][j][r] = 0.f;

    // per-thread ldmatrix row components (fixed across k)
    const int a_row_l = lane & 15;           // within m16 tile
    const int a_coff = lane >> 4;            // +0/+1 k-chunk
    const int b_row_l = ((lane >> 4) << 3) + (lane & 7);  // within n16 pair
    const int b_coff = (lane >> 3) & 1;

    load_chunk(0);
    #pragma unroll 1
    for (int kt = 0; kt < KCH; kt++) {
        if (kt + 1 < KCH) { load_chunk(kt + 1); CP_WAIT(1); }
        else CP_WAIT(0);
        __syncthreads();
        const uint32_t Ab = base + (kt & 1) * 2 * TILE_B;
        const uint32_t Bb = Ab + TILE_B;
        #pragma unroll
        for (int ks = 0; ks < 4; ks++) {
            uint32_t a[2][4], b[4][4];
            #pragma unroll
            for (int mt = 0; mt < 2; mt++) {
                int row = wm + mt * 16 + a_row_l;
                int kc = ks * 2 + a_coff;
                ldsm4(a[mt][0], a[mt][1], a[mt][2], a[mt][3],
                      Ab + (uint32_t)(row * 128 + ((kc ^ (row & 7)) * 16)));
            }
            #pragma unroll
            for (int p = 0; p < 4; p++) {
                int row = wn + p * 16 + b_row_l;
                int kc = ks * 2 + b_coff;
                ldsm4(b[p][0], b[p][1], b[p][2], b[p][3],
                      Bb + (uint32_t)(row * 128 + ((kc ^ (row & 7)) * 16)));
            }
            #pragma unroll
            for (int mt = 0; mt < 2; mt++)
                #pragma unroll
                for (int p = 0; p < 4; p++) {
                    mma16816(acc[mt][2 * p + 0], a[mt], b[p][0], b[p][1]);
                    mma16816(acc[mt][2 * p + 1], a[mt], b[p][2], b[p][3]);
                }
        }
        __syncthreads();
    }

    // epilogue: scale rows, write transposed logitsT[c][m]
    #pragma unroll
    for (int mt = 0; mt < 2; mt++) {
        const int row0 = bm + wm + mt * 16 + (lane >> 2);
        const int row1 = row0 + 8;
        const float s0 = g_scale[row0];
        const float s1 = g_scale[row1];
        #pragma unroll
        for (int j = 0; j < 8; j++) {
            int c0 = bn + wn + (j >> 1) * 16 + (j & 1) * 8 + (lane & 3) * 2;
            if (c0 + 1 < CC) {
                g_logitsT[(size_t)c0 * MM + row0]       = s0 * acc[mt][j][0];
                g_logitsT[(size_t)(c0 + 1) * MM + row0] = s0 * acc[mt][j][1];
                g_logitsT[(size_t)c0 * MM + row1]       = s1 * acc[mt][j][2];
                g_logitsT[(size_t)(c0 + 1) * MM + row1] = s1 * acc[mt][j][3];
            } else if (c0 < CC) {
                g_logitsT[(size_t)c0 * MM + row0] = s0 * acc[mt][j][0];
                g_logitsT[(size_t)c0 * MM + row1] = s1 * acc[mt][j][2];
            }
        }
    }
}

// ---------------- 4. online-softmax LSE, thread per row (coalesced col walk) ----------
__global__ void __launch_bounds__(256) lse_kernel(const int* __restrict__ labeling) {
    const int m = blockIdx.x * 256 + threadIdx.x;
    float mx = -1e30f, ssum = 0.f;
    const float* p = g_logitsT + m;
    #pragma unroll 4
    for (int c = 0; c < CC; c++) {
        float x = __ldg(p + (size_t)c * MM);
        if (x > mx) { ssum = ssum * __expf(mx - x) + 1.f; mx = x; }
        else        { ssum += __expf(x - mx); }
    }
    const float lse = mx + __logf(ssum);
    const int n = m & 31;
    g_lp[m] = __ldg(p) - lse;                                    // blank
    #pragma unroll
    for (int i = 1; i <= SS; i++) {
        int cls = labeling[n * SS + i - 1];
        g_lp[(size_t)i * MM + m] = __ldg(p + (size_t)cls * MM) - lse;
    }
}

// ---------------- 5. CTC: one warp per sample, shfl recursion, smem-staged lp --------
__global__ void __launch_bounds__(128) ctc_kernel(const int* __restrict__ labeling,
                                                  const int* __restrict__ in_lens,
                                                  const int* __restrict__ lab_lens) {
    extern __shared__ float slp[];                 // [512][32]
    const int n = blockIdx.x;
    const int tid = threadIdx.x;
    for (int idx = tid; idx < TT * 32; idx += 128) {
        int t = idx >> 5, i = idx & 31;
        slp[idx] = g_lp[(size_t)i * MM + (t << 5) + n];
    }
    __syncthreads();
    if (tid >= 32) return;
    const int l = tid;                             // lane: states 2l, 2l+1
    bool skip = false;
    if (l >= 1 && l < SS)
        skip = labeling[n * SS + l] != labeling[n * SS + l - 1];
    const bool odd_valid = (l < 30);
    float e = (l == 0) ? slp[0] : NEGINF;
    float o = (l == 0) ? slp[1] : NEGINF;
    const int Tn = in_lens[n];
    for (int t = 1; t < Tn; t++) {
        float po = __shfl_up_sync(0xffffffffu, o, 1);  // alpha[2l-1]
        if (l == 0) po = NEGINF;
        float lpb = slp[t << 5];
        float lpo = odd_valid ? slp[(t << 5) + 1 + l] : NEGINF;
        float m1 = fmaxf(e, po);
        float ne = m1 + __logf(__expf(e - m1) + __expf(po - m1)) + lpb;
        float a3 = skip ? po : NEGINF;
        float m2 = fmaxf(o, fmaxf(e, a3));
        float no = m2 + __logf(__expf(o - m2) + __expf(e - m2) + __expf(a3 - m2)) + lpo;
        e = ne; o = no;
    }
    const int labn = lab_lens[n];
    float x = __shfl_sync(0xffffffffu, e, labn);       // alpha[2*labn]
    float y = __shfl_sync(0xffffffffu, o, labn - 1);   // alpha[2*labn-1]
    if (l == 0) {
        float m = fmaxf(x, y);
        g_nll[n] = -(m + __logf(__expf(x - m) + __expf(y - m)));
    }
}

// ---------------- 6. deterministic sum ----------------
__global__ void sum_kernel(float* __restrict__ out) {
    if (threadIdx.x == 0) {
        float t = 0.f;
        #pragma unroll
        for (int i = 0; i < NN; i++) t += g_nll[i];
        out[0] = t;
    }
}

// ---------------- launch ----------------
extern "C" void kernel_launch(void* const* d_in, const int* in_sizes, int n_in,
                              void* d_out, int out_size) {
    const float* feats = (const float*)d_in[0];
    const float* weight = (const float*)d_in[1];
    const int* labeling = (const int*)d_in[2];
    const int* logit_lgts = (const int*)d_in[3];
    const int* labeling_lgts = (const int*)d_in[4];
    float* out = (float*)d_out;

    cudaFuncSetAttribute(gemm_kernel, cudaFuncAttributeMaxDynamicSharedMemorySize, GEMM_SMEM);
    cudaFuncSetAttribute(ctc_kernel, cudaFuncAttributeMaxDynamicSharedMemorySize, TT * 32 * 4);

    wnorm_kernel<<<CPAD / 256, 256>>>(weight);
    fscale_kernel<<<MM / 8, 256>>>(feats);
    gemm_kernel<<<dim3(CPAD / 128, MM / 128), 256, GEMM_SMEM>>>();  // 12 x 128 blocks
    lse_kernel<<<MM / 256, 256>>>(labeling);
    ctc_kernel<<<NN, 128, TT * 32 * 4>>>(labeling, logit_lgts, labeling_lgts);
    sum_kernel<<<1, 32>>>(out);
}

// round 6
// speedup vs baseline: 1.5143x; 1.2101x over previous
#include <cuda_runtime.h>
#include <cuda_bf16.h>
#include <math.h>
#include <stdint.h>

// Problem constants
#define TT 512
#define NN 32
#define CC 1296
#define DD 512
#define SS 30
#define LL 61
#define MM (TT*NN)              // 16384
#define NORM_SCALE 32.0f
#define NEGINF (-1e9f)
#define CPAD 1536
#define NCB 12                  // C blocks of 128

// ---------------- scratch ----------------
__device__ __nv_bfloat16 g_fb[(size_t)MM * DD];     // feats bf16 [m][d]
__device__ __nv_bfloat16 g_wb[(size_t)CPAD * DD];   // normalized weight transposed [c][d]
__device__ float g_scale[MM];
__device__ float g_logitsT[(size_t)CC * MM];        // logits transposed [c][m]
__device__ float g_psum[(size_t)NCB * MM];          // per-cblock sum of exp(logit-32)
__device__ float g_lp[32 * MM];                     // [i][m]: i=0 blank, 1..30 labels
__device__ float g_nll[NN];

// ---------------- helpers ----------------
__device__ __forceinline__ uint32_t smem_u32(const void* p) {
    uint32_t a;
    asm("{ .reg .u64 t; cvta.to.shared.u64 t, %1; cvt.u32.u64 %0, t; }" : "=r"(a) : "l"(p));
    return a;
}
__device__ __forceinline__ void cp_async16(uint32_t sa, const void* ga) {
    asm volatile("cp.async.cg.shared.global [%0], [%1], 16;" :: "r"(sa), "l"(ga) : "memory");
}
#define CP_COMMIT() asm volatile("cp.async.commit_group;" ::: "memory")
#define CP_WAIT(n)  asm volatile("cp.async.wait_group %0;" :: "n"(n) : "memory")

__device__ __forceinline__ void ldsm4(uint32_t& r0, uint32_t& r1, uint32_t& r2, uint32_t& r3,
                                      uint32_t addr) {
    asm volatile("ldmatrix.sync.aligned.m8n8.x4.shared.b16 {%0,%1,%2,%3}, [%4];"
                 : "=r"(r0), "=r"(r1), "=r"(r2), "=r"(r3) : "r"(addr));
}
__device__ __forceinline__ void mma16816(float* d, const uint32_t* a, uint32_t b0, uint32_t b1) {
    asm volatile("mma.sync.aligned.m16n8k16.row.col.f32.bf16.bf16.f32 "
                 "{%0,%1,%2,%3}, {%4,%5,%6,%7}, {%8,%9}, {%0,%1,%2,%3};"
                 : "+f"(d[0]), "+f"(d[1]), "+f"(d[2]), "+f"(d[3])
                 : "r"(a[0]), "r"(a[1]), "r"(a[2]), "r"(a[3]), "r"(b0), "r"(b1));
}

// ---------------- 1. normalize weight columns -> transposed bf16 [c][d] ----------------
__global__ void wnorm_kernel(const float* __restrict__ w) {
    int c = blockIdx.x * blockDim.x + threadIdx.x;
    if (c >= CPAD) return;
    if (c >= CC) {
        for (int d = 0; d < DD; d++) g_wb[(size_t)c * DD + d] = __float2bfloat16(0.f);
        return;
    }
    float ss = 0.f;
    #pragma unroll 8
    for (int d = 0; d < DD; d++) { float v = w[d * CC + c]; ss += v * v; }
    float inv = rsqrtf(ss);
    #pragma unroll 8
    for (int d = 0; d < DD; d++)
        g_wb[(size_t)c * DD + d] = __float2bfloat16(w[d * CC + c] * inv);
}

// ---------------- 2. per-row scale + bf16 convert ----------------
__global__ void fscale_kernel(const float* __restrict__ f) {
    int row = blockIdx.x * (blockDim.x >> 5) + (threadIdx.x >> 5);
    int lane = threadIdx.x & 31;
    if (row >= MM) return;
    const float4* fr = (const float4*)(f + (size_t)row * DD);
    __nv_bfloat16* ob = g_fb + (size_t)row * DD;
    float ss = 0.f;
    #pragma unroll
    for (int i = lane; i < DD / 4; i += 32) {
        float4 v = fr[i];
        ss += v.x * v.x + v.y * v.y + v.z * v.z + v.w * v.w;
        ob[i * 4 + 0] = __float2bfloat16(v.x);
        ob[i * 4 + 1] = __float2bfloat16(v.y);
        ob[i * 4 + 2] = __float2bfloat16(v.z);
        ob[i * 4 + 3] = __float2bfloat16(v.w);
    }
    #pragma unroll
    for (int o = 16; o; o >>= 1) ss += __shfl_xor_sync(0xffffffffu, ss, o);
    if (lane == 0) g_scale[row] = NORM_SCALE * rsqrtf(ss);
}

// ---------------- 3. bf16 mma.sync GEMM + fused exp-partial epilogue ----------------
// Block tile: 256m x 128n, BK=64, 256 threads = 8 warps (4m x 2n), warp tile 64x64.
#define GBK 64
#define KCH (DD / GBK)          // 8
#define A_TILE_B 32768          // 256 rows * 128B
#define B_TILE_B 16384          // 128 rows * 128B
#define BUF_B (A_TILE_B + B_TILE_B)
#define GEMM_SMEM (2 * BUF_B + 1024)

__global__ void __launch_bounds__(256) gemm_kernel() {
    extern __shared__ char smraw[];
    const uint32_t base = (smem_u32(smraw) + 1023u) & ~1023u;
    const int tid = threadIdx.x;
    const int wid = tid >> 5;
    const int lane = tid & 31;
    const int bm = blockIdx.y * 256;
    const int bn = blockIdx.x * 128;
    const int wm = (wid >> 1) * 64;
    const int wn = (wid & 1) * 64;

    auto load_chunk = [&](int kt) {
        uint32_t Ab = base + (kt & 1) * BUF_B;
        uint32_t Bb = Ab + A_TILE_B;
        const char* Ag = (const char*)g_fb + (size_t)bm * 1024 + (size_t)kt * 128;
        const char* Bg = (const char*)g_wb + (size_t)bn * 1024 + (size_t)kt * 128;
        #pragma unroll
        for (int r = 0; r < 8; r++) {              // A: 2048 chunks
            int s = tid + r * 256;
            int row = s >> 3, kc = s & 7;
            cp_async16(Ab + (uint32_t)(row * 128 + ((kc ^ (row & 7)) * 16)),
                       Ag + (size_t)row * 1024 + kc * 16);
        }
        #pragma unroll
        for (int r = 0; r < 4; r++) {              // B: 1024 chunks
            int s = tid + r * 256;
            int row = s >> 3, kc = s & 7;
            cp_async16(Bb + (uint32_t)(row * 128 + ((kc ^ (row & 7)) * 16)),
                       Bg + (size_t)row * 1024 + kc * 16);
        }
        CP_COMMIT();
    };

    float acc[4][8][4];
    #pragma unroll
    for (int i = 0; i < 4; i++)
        #pragma unroll
        for (int j = 0; j < 8; j++)
            #pragma unroll
            for (int r = 0; r < 4; r++) acc[i][j][r] = 0.f;

    const int a_row_l = lane & 15;
    const int a_coff = lane >> 4;
    const int b_row_l = ((lane >> 4) << 3) + (lane & 7);
    const int b_coff = (lane >> 3) & 1;

    load_chunk(0);
    #pragma unroll 1
    for (int kt = 0; kt < KCH; kt++) {
        if (kt + 1 < KCH) { load_chunk(kt + 1); CP_WAIT(1); }
        else CP_WAIT(0);
        __syncthreads();
        const uint32_t Ab = base + (kt & 1) * BUF_B;
        const uint32_t Bb = Ab + A_TILE_B;
        #pragma unroll
        for (int ks = 0; ks < 4; ks++) {
            uint32_t a[4][4], b[4][4];
            #pragma unroll
            for (int mt = 0; mt < 4; mt++) {
                int row = wm + mt * 16 + a_row_l;
                int kc = ks * 2 + a_coff;
                ldsm4(a[mt][0], a[mt][1], a[mt][2], a[mt][3],
                      Ab + (uint32_t)(row * 128 + ((kc ^ (row & 7)) * 16)));
            }
            #pragma unroll
            for (int p = 0; p < 4; p++) {
                int row = wn + p * 16 + b_row_l;
                int kc = ks * 2 + b_coff;
                ldsm4(b[p][0], b[p][1], b[p][2], b[p][3],
                      Bb + (uint32_t)(row * 128 + ((kc ^ (row & 7)) * 16)));
            }
            #pragma unroll
            for (int mt = 0; mt < 4; mt++)
                #pragma unroll
                for (int p = 0; p < 4; p++) {
                    mma16816(acc[mt][2 * p + 0], a[mt], b[p][0], b[p][1]);
                    mma16816(acc[mt][2 * p + 1], a[mt], b[p][2], b[p][3]);
                }
        }
        __syncthreads();
    }

    // epilogue: scale, write logitsT, fused per-row sum of exp(logit-32)
    float* ps = (float*)smraw;                      // [256 rows][2 n-warps]
    #pragma unroll
    for (int mt = 0; mt < 4; mt++) {
        const int lr0 = wm + mt * 16 + (lane >> 2); // local row
        const int lr1 = lr0 + 8;
        const int row0 = bm + lr0, row1 = bm + lr1;
        const float s0 = g_scale[row0];
        const float s1 = g_scale[row1];
        float e0 = 0.f, e1 = 0.f;
        #pragma unroll
        for (int j = 0; j < 8; j++) {
            int c0 = bn + wn + (j >> 1) * 16 + (j & 1) * 8 + (lane & 3) * 2;
            float v00 = s0 * acc[mt][j][0], v01 = s0 * acc[mt][j][1];
            float v10 = s1 * acc[mt][j][2], v11 = s1 * acc[mt][j][3];
            if (c0 < CC) {
                g_logitsT[(size_t)c0 * MM + row0] = v00;
                g_logitsT[(size_t)c0 * MM + row1] = v10;
                e0 += __expf(v00 - 32.f);
                e1 += __expf(v10 - 32.f);
            }
            if (c0 + 1 < CC) {
                g_logitsT[(size_t)(c0 + 1) * MM + row0] = v01;
                g_logitsT[(size_t)(c0 + 1) * MM + row1] = v11;
                e0 += __expf(v01 - 32.f);
                e1 += __expf(v11 - 32.f);
            }
        }
        // quad reduce (lanes l^1, l^2 share the same rows)
        e0 += __shfl_xor_sync(0xffffffffu, e0, 1);
        e0 += __shfl_xor_sync(0xffffffffu, e0, 2);
        e1 += __shfl_xor_sync(0xffffffffu, e1, 1);
        e1 += __shfl_xor_sync(0xffffffffu, e1, 2);
        if ((lane & 3) == 0) {
            ps[lr0 * 2 + (wid & 1)] = e0;
            ps[lr1 * 2 + (wid & 1)] = e1;
        }
    }
    __syncthreads();
    // 256 threads: one row each -> write partial sum for this c-block
    g_psum[(size_t)blockIdx.x * MM + bm + tid] = ps[tid * 2] + ps[tid * 2 + 1];
}

// ---------------- 4. combine partials -> lse; gather needed classes ----------------
__global__ void __launch_bounds__(256) lsegather_kernel(const int* __restrict__ labeling) {
    const int m = blockIdx.x * 256 + threadIdx.x;
    float ssum = 0.f;
    #pragma unroll
    for (int cb = 0; cb < NCB; cb++) ssum += g_psum[(size_t)cb * MM + m];
    const float lse = 32.f + __logf(ssum);
    const int n = m & 31;
    const float* p = g_logitsT + m;
    g_lp[m] = __ldg(p) - lse;                                    // blank
    #pragma unroll
    for (int i = 1; i <= SS; i++) {
        int cls = labeling[n * SS + i - 1];
        g_lp[(size_t)i * MM + m] = __ldg(p + (size_t)cls * MM) - lse;
    }
}

// ---------------- 5. CTC: one warp per sample, shfl recursion, smem-staged lp --------
__global__ void __launch_bounds__(128) ctc_kernel(const int* __restrict__ labeling,
                                                  const int* __restrict__ in_lens,
                                                  const int* __restrict__ lab_lens) {
    extern __shared__ float slp[];                 // [512][32]
    const int n = blockIdx.x;
    const int tid = threadIdx.x;
    for (int idx = tid; idx < TT * 32; idx += 128) {
        int t = idx >> 5, i = idx & 31;
        slp[idx] = g_lp[(size_t)i * MM + (t << 5) + n];
    }
    __syncthreads();
    if (tid >= 32) return;
    const int l = tid;
    bool skip = false;
    if (l >= 1 && l < SS)
        skip = labeling[n * SS + l] != labeling[n * SS + l - 1];
    const bool odd_valid = (l < 30);
    float e = (l == 0) ? slp[0] : NEGINF;
    float o = (l == 0) ? slp[1] : NEGINF;
    const int Tn = in_lens[n];
    for (int t = 1; t < Tn; t++) {
        float po = __shfl_up_sync(0xffffffffu, o, 1);
        if (l == 0) po = NEGINF;
        float lpb = slp[t << 5];
        float lpo = odd_valid ? slp[(t << 5) + 1 + l] : NEGINF;
        float m1 = fmaxf(e, po);
        float ne = m1 + __logf(__expf(e - m1) + __expf(po - m1)) + lpb;
        float a3 = skip ? po : NEGINF;
        float m2 = fmaxf(o, fmaxf(e, a3));
        float no = m2 + __logf(__expf(o - m2) + __expf(e - m2) + __expf(a3 - m2)) + lpo;
        e = ne; o = no;
    }
    const int labn = lab_lens[n];
    float x = __shfl_sync(0xffffffffu, e, labn);
    float y = __shfl_sync(0xffffffffu, o, labn - 1);
    if (l == 0) {
        float m = fmaxf(x, y);
        g_nll[n] = -(m + __logf(__expf(x - m) + __expf(y - m)));
    }
}

// ---------------- 6. deterministic sum ----------------
__global__ void sum_kernel(float* __restrict__ out) {
    if (threadIdx.x == 0) {
        float t = 0.f;
        #pragma unroll
        for (int i = 0; i < NN; i++) t += g_nll[i];
        out[0] = t;
    }
}

// ---------------- launch ----------------
extern "C" void kernel_launch(void* const* d_in, const int* in_sizes, int n_in,
                              void* d_out, int out_size) {
    const float* feats = (const float*)d_in[0];
    const float* weight = (const float*)d_in[1];
    const int* labeling = (const int*)d_in[2];
    const int* logit_lgts = (const int*)d_in[3];
    const int* labeling_lgts = (const int*)d_in[4];
    float* out = (float*)d_out;

    cudaFuncSetAttribute(gemm_kernel, cudaFuncAttributeMaxDynamicSharedMemorySize, GEMM_SMEM);
    cudaFuncSetAttribute(ctc_kernel, cudaFuncAttributeMaxDynamicSharedMemorySize, TT * 32 * 4);

    wnorm_kernel<<<CPAD / 256, 256>>>(weight);
    fscale_kernel<<<MM / 8, 256>>>(feats);
    gemm_kernel<<<dim3(NCB, MM / 256), 256, GEMM_SMEM>>>();   // 12 x 64 blocks
    lsegather_kernel<<<MM / 256, 256>>>(labeling);
    ctc_kernel<<<NN, 128, TT * 32 * 4>>>(labeling, logit_lgts, labeling_lgts);
    sum_kernel<<<1, 32>>>(out);
}

// round 7
// speedup vs baseline: 3.1682x; 2.0921x over previous
#include <cuda_runtime.h>
#include <cuda_bf16.h>
#include <math.h>
#include <stdint.h>

// Problem constants
#define TT 512
#define NN 32
#define CC 1296
#define DD 512
#define SS 30
#define LL 61
#define MM (TT*NN)              // 16384
#define NORM_SCALE 32.0f
#define NEGINF (-1e9f)
#define NCB 11                  // n-blocks of 128
#define CPAD (NCB * 128)        // 1408

// ---------------- scratch ----------------
__device__ __nv_bfloat16 g_fb[(size_t)MM * DD];     // feats bf16 [m][d]
__device__ __nv_bfloat16 g_wb[(size_t)CPAD * DD];   // normalized weight transposed [c][d]
__device__ float g_scale[MM];
__device__ float g_logitsT[(size_t)CC * MM];        // logits transposed [c][m]
__device__ float g_psum[(size_t)NCB * MM];          // per-cblock sum of exp(logit-32)
__device__ float g_lp[32 * MM];                     // [i][m]: i=0 blank, 1..30 labels
__device__ float g_nll[NN];

// ---------------- helpers ----------------
__device__ __forceinline__ uint32_t smem_u32(const void* p) {
    uint32_t a;
    asm("{ .reg .u64 t; cvta.to.shared.u64 t, %1; cvt.u32.u64 %0, t; }" : "=r"(a) : "l"(p));
    return a;
}
__device__ __forceinline__ void cp_async16(uint32_t sa, const void* ga) {
    asm volatile("cp.async.cg.shared.global [%0], [%1], 16;" :: "r"(sa), "l"(ga) : "memory");
}
#define CP_COMMIT() asm volatile("cp.async.commit_group;" ::: "memory")
#define CP_WAIT(n)  asm volatile("cp.async.wait_group %0;" :: "n"(n) : "memory")

__device__ __forceinline__ void ldsm4(uint32_t& r0, uint32_t& r1, uint32_t& r2, uint32_t& r3,
                                      uint32_t addr) {
    asm volatile("ldmatrix.sync.aligned.m8n8.x4.shared.b16 {%0,%1,%2,%3}, [%4];"
                 : "=r"(r0), "=r"(r1), "=r"(r2), "=r"(r3) : "r"(addr));
}
__device__ __forceinline__ void mma16816(float* d, const uint32_t* a, uint32_t b0, uint32_t b1) {
    asm volatile("mma.sync.aligned.m16n8k16.row.col.f32.bf16.bf16.f32 "
                 "{%0,%1,%2,%3}, {%4,%5,%6,%7}, {%8,%9}, {%0,%1,%2,%3};"
                 : "+f"(d[0]), "+f"(d[1]), "+f"(d[2]), "+f"(d[3])
                 : "r"(a[0]), "r"(a[1]), "r"(a[2]), "r"(a[3]), "r"(b0), "r"(b1));
}

// ---------------- 1. normalize weight columns -> transposed bf16 [c][d] ----------------
__global__ void wnorm_kernel(const float* __restrict__ w) {
    int c = blockIdx.x * blockDim.x + threadIdx.x;
    if (c >= CPAD) return;
    if (c >= CC) {
        for (int d = 0; d < DD; d++) g_wb[(size_t)c * DD + d] = __float2bfloat16(0.f);
        return;
    }
    float ss = 0.f;
    #pragma unroll 8
    for (int d = 0; d < DD; d++) { float v = w[d * CC + c]; ss += v * v; }
    float inv = rsqrtf(ss);
    #pragma unroll 8
    for (int d = 0; d < DD; d++)
        g_wb[(size_t)c * DD + d] = __float2bfloat16(w[d * CC + c] * inv);
}

// ---------------- 2. per-row scale + bf16 convert ----------------
__global__ void fscale_kernel(const float* __restrict__ f) {
    int row = blockIdx.x * (blockDim.x >> 5) + (threadIdx.x >> 5);
    int lane = threadIdx.x & 31;
    if (row >= MM) return;
    const float4* fr = (const float4*)(f + (size_t)row * DD);
    __nv_bfloat16* ob = g_fb + (size_t)row * DD;
    float ss = 0.f;
    #pragma unroll
    for (int i = lane; i < DD / 4; i += 32) {
        float4 v = fr[i];
        ss += v.x * v.x + v.y * v.y + v.z * v.z + v.w * v.w;
        ob[i * 4 + 0] = __float2bfloat16(v.x);
        ob[i * 4 + 1] = __float2bfloat16(v.y);
        ob[i * 4 + 2] = __float2bfloat16(v.z);
        ob[i * 4 + 3] = __float2bfloat16(v.w);
    }
    #pragma unroll
    for (int o = 16; o; o >>= 1) ss += __shfl_xor_sync(0xffffffffu, ss, o);
    if (lane == 0) g_scale[row] = NORM_SCALE * rsqrtf(ss);
}

// ---------------- 3. bf16 mma.sync GEMM + fused exp-partial epilogue ----------------
// Block tile: 128m x 128n, BK=64, 256 threads = 8 warps (4m x 2n), warp tile 32x64.
#define GBK 64
#define KCH (DD / GBK)          // 8
#define TILE_B 16384            // 128 rows * 128B
#define GEMM_SMEM (2 * 2 * TILE_B + 1024)

__global__ void __launch_bounds__(256, 2) gemm_kernel() {
    extern __shared__ char smraw[];
    const uint32_t base = (smem_u32(smraw) + 1023u) & ~1023u;
    const int tid = threadIdx.x;
    const int wid = tid >> 5;
    const int lane = tid & 31;
    const int bm = blockIdx.y * 128;
    const int bn = blockIdx.x * 128;
    const int wm = (wid >> 1) * 32;
    const int wn = (wid & 1) * 64;

    auto load_tile = [&](uint32_t sbuf, const __nv_bfloat16* gsrc, int kt) {
        const char* g = (const char*)gsrc + (size_t)kt * 128;
        #pragma unroll
        for (int r = 0; r < 4; r++) {
            int s = tid + r * 256;
            int row = s >> 3, kc = s & 7;
            cp_async16(sbuf + (uint32_t)(row * 128 + ((kc ^ (row & 7)) * 16)),
                       g + (size_t)row * 1024 + kc * 16);
        }
    };
    auto load_chunk = [&](int kt) {
        uint32_t off = (kt & 1) * 2 * TILE_B;
        load_tile(base + off, g_fb + (size_t)bm * DD, kt);
        load_tile(base + off + TILE_B, g_wb + (size_t)bn * DD, kt);
        CP_COMMIT();
    };

    float acc[2][8][4];
    #pragma unroll
    for (int i = 0; i < 2; i++)
        #pragma unroll
        for (int j = 0; j < 8; j++)
            #pragma unroll
            for (int r = 0; r < 4; r++) acc[i][j][r] = 0.f;

    const int a_row_l = lane & 15;
    const int a_coff = lane >> 4;
    const int b_row_l = ((lane >> 4) << 3) + (lane & 7);
    const int b_coff = (lane >> 3) & 1;

    load_chunk(0);
    #pragma unroll 1
    for (int kt = 0; kt < KCH; kt++) {
        if (kt + 1 < KCH) { load_chunk(kt + 1); CP_WAIT(1); }
        else CP_WAIT(0);
        __syncthreads();
        const uint32_t Ab = base + (kt & 1) * 2 * TILE_B;
        const uint32_t Bb = Ab + TILE_B;
        #pragma unroll
        for (int ks = 0; ks < 4; ks++) {
            uint32_t a[2][4], b[4][4];
            #pragma unroll
            for (int mt = 0; mt < 2; mt++) {
                int row = wm + mt * 16 + a_row_l;
                int kc = ks * 2 + a_coff;
                ldsm4(a[mt][0], a[mt][1], a[mt][2], a[mt][3],
                      Ab + (uint32_t)(row * 128 + ((kc ^ (row & 7)) * 16)));
            }
            #pragma unroll
            for (int p = 0; p < 4; p++) {
                int row = wn + p * 16 + b_row_l;
                int kc = ks * 2 + b_coff;
                ldsm4(b[p][0], b[p][1], b[p][2], b[p][3],
                      Bb + (uint32_t)(row * 128 + ((kc ^ (row & 7)) * 16)));
            }
            #pragma unroll
            for (int mt = 0; mt < 2; mt++)
                #pragma unroll
                for (int p = 0; p < 4; p++) {
                    mma16816(acc[mt][2 * p + 0], a[mt], b[p][0], b[p][1]);
                    mma16816(acc[mt][2 * p + 1], a[mt], b[p][2], b[p][3]);
                }
        }
        __syncthreads();
    }

    // epilogue: scale, write logitsT, fused per-row sum of exp(logit-32)
    float* ps = (float*)smraw;                      // [128 rows][2 n-warps]
    #pragma unroll
    for (int mt = 0; mt < 2; mt++) {
        const int lr0 = wm + mt * 16 + (lane >> 2);
        const int lr1 = lr0 + 8;
        const int row0 = bm + lr0, row1 = bm + lr1;
        const float s0 = g_scale[row0];
        const float s1 = g_scale[row1];
        float e0 = 0.f, e1 = 0.f;
        #pragma unroll
        for (int j = 0; j < 8; j++) {
            int c0 = bn + wn + (j >> 1) * 16 + (j & 1) * 8 + (lane & 3) * 2;
            float v00 = s0 * acc[mt][j][0], v01 = s0 * acc[mt][j][1];
            float v10 = s1 * acc[mt][j][2], v11 = s1 * acc[mt][j][3];
            if (c0 < CC) {
                g_logitsT[(size_t)c0 * MM + row0] = v00;
                g_logitsT[(size_t)c0 * MM + row1] = v10;
                e0 += __expf(v00 - 32.f);
                e1 += __expf(v10 - 32.f);
            }
            if (c0 + 1 < CC) {
                g_logitsT[(size_t)(c0 + 1) * MM + row0] = v01;
                g_logitsT[(size_t)(c0 + 1) * MM + row1] = v11;
                e0 += __expf(v01 - 32.f);
                e1 += __expf(v11 - 32.f);
            }
        }
        e0 += __shfl_xor_sync(0xffffffffu, e0, 1);
        e0 += __shfl_xor_sync(0xffffffffu, e0, 2);
        e1 += __shfl_xor_sync(0xffffffffu, e1, 1);
        e1 += __shfl_xor_sync(0xffffffffu, e1, 2);
        if ((lane & 3) == 0) {
            ps[lr0 * 2 + (wid & 1)] = e0;
            ps[lr1 * 2 + (wid & 1)] = e1;
        }
    }
    __syncthreads();
    if (tid < 128)
        g_psum[(size_t)blockIdx.x * MM + bm + tid] = ps[tid * 2] + ps[tid * 2 + 1];
}

// ---------------- 4. combine partials -> lse; gather needed classes ----------------
__global__ void __launch_bounds__(256) lsegather_kernel(const int* __restrict__ labeling) {
    const int m = blockIdx.x * 256 + threadIdx.x;
    float ssum = 0.f;
    #pragma unroll
    for (int cb = 0; cb < NCB; cb++) ssum += g_psum[(size_t)cb * MM + m];
    const float lse = 32.f + __logf(ssum);
    const int n = m & 31;
    const float* p = g_logitsT + m;
    g_lp[m] = __ldg(p) - lse;                                    // blank
    #pragma unroll
    for (int i = 1; i <= SS; i++) {
        int cls = labeling[n * SS + i - 1];
        g_lp[(size_t)i * MM + m] = __ldg(p + (size_t)cls * MM) - lse;
    }
}

// ---------------- 5. CTC: one warp per sample, shfl recursion, smem-staged lp --------
__global__ void __launch_bounds__(128) ctc_kernel(const int* __restrict__ labeling,
                                                  const int* __restrict__ in_lens,
                                                  const int* __restrict__ lab_lens) {
    extern __shared__ float slp[];                 // [512][32]
    const int n = blockIdx.x;
    const int tid = threadIdx.x;
    for (int idx = tid; idx < TT * 32; idx += 128) {
        int t = idx >> 5, i = idx & 31;
        slp[idx] = g_lp[(size_t)i * MM + (t << 5) + n];
    }
    __syncthreads();
    if (tid >= 32) return;
    const int l = tid;
    bool skip = false;
    if (l >= 1 && l < SS)
        skip = labeling[n * SS + l] != labeling[n * SS + l - 1];
    const bool odd_valid = (l < 30);
    float e = (l == 0) ? slp[0] : NEGINF;
    float o = (l == 0) ? slp[1] : NEGINF;
    const int Tn = in_lens[n];
    for (int t = 1; t < Tn; t++) {
        float po = __shfl_up_sync(0xffffffffu, o, 1);
        if (l == 0) po = NEGINF;
        float lpb = slp[t << 5];
        float lpo = odd_valid ? slp[(t << 5) + 1 + l] : NEGINF;
        float m1 = fmaxf(e, po);
        float ne = m1 + __logf(__expf(e - m1) + __expf(po - m1)) + lpb;
        float a3 = skip ? po : NEGINF;
        float m2 = fmaxf(o, fmaxf(e, a3));
        float no = m2 + __logf(__expf(o - m2) + __expf(e - m2) + __expf(a3 - m2)) + lpo;
        e = ne; o = no;
    }
    const int labn = lab_lens[n];
    float x = __shfl_sync(0xffffffffu, e, labn);
    float y = __shfl_sync(0xffffffffu, o, labn - 1);
    if (l == 0) {
        float m = fmaxf(x, y);
        g_nll[n] = -(m + __logf(__expf(x - m) + __expf(y - m)));
    }
}

// ---------------- 6. deterministic sum ----------------
__global__ void sum_kernel(float* __restrict__ out) {
    if (threadIdx.x == 0) {
        float t = 0.f;
        #pragma unroll
        for (int i = 0; i < NN; i++) t += g_nll[i];
        out[0] = t;
    }
}

// ---------------- launch ----------------
extern "C" void kernel_launch(void* const* d_in, const int* in_sizes, int n_in,
                              void* d_out, int out_size) {
    const float* feats = (const float*)d_in[0];
    const float* weight = (const float*)d_in[1];
    const int* labeling = (const int*)d_in[2];
    const int* logit_lgts = (const int*)d_in[3];
    const int* labeling_lgts = (const int*)d_in[4];
    float* out = (float*)d_out;

    cudaFuncSetAttribute(gemm_kernel, cudaFuncAttributeMaxDynamicSharedMemorySize, GEMM_SMEM);
    cudaFuncSetAttribute(ctc_kernel, cudaFuncAttributeMaxDynamicSharedMemorySize, TT * 32 * 4);

    wnorm_kernel<<<CPAD / 128, 128>>>(weight);
    fscale_kernel<<<MM / 8, 256>>>(feats);
    gemm_kernel<<<dim3(NCB, MM / 128), 256, GEMM_SMEM>>>();   // 11 x 128 blocks
    lsegather_kernel<<<MM / 256, 256>>>(labeling);
    ctc_kernel<<<NN, 128, TT * 32 * 4>>>(labeling, logit_lgts, labeling_lgts);
    sum_kernel<<<1, 32>>>(out);
}